// round 11
// baseline (speedup 1.0000x reference)
#include <cuda_runtime.h>
#include <cuda_bf16.h>
#include <math.h>
#include <stdint.h>

#define NN 100000
#define EE 1600000
#define DH 128
#define GG 64
#define CC 10
#define NT 782               // ceil(NN/128)
#define NPAD (NT * 128)      // 100096
#define SCB 98               // scan blocks: ceil(NN/1024)

// ---------------- scratch (static device arrays; allocation forbidden) ------
__device__ float g_hA[NPAD * DH];      // layer 0 output
__device__ float g_hB[NPAD * DH];      // layer 1 output
__device__ float g_hpool[NPAD * DH];   // relu(u) after layer 2 for pooling
__device__ __nv_bfloat16 g_Wthi[6 * DH * DH];  // weights transposed [n][k], bf16 hi
__device__ __nv_bfloat16 g_Wtlo[6 * DH * DH];  // bf16 lo plane
__device__ int   g_counts[NN];
__device__ int   g_rowptr[NN + 1];
__device__ int   g_cur[NN];
__device__ int   g_csr_src[EE];
__device__ int   g_bsum[SCB];
__device__ int   g_boff[SCB];
__device__ int   g_gstart[GG + 1];
__device__ float g_pool[GG * DH];

// ---------------- helpers ----------------------------------------------------
__device__ __forceinline__ void split2(float a, float b, uint32_t& hw, uint32_t& lw) {
    __nv_bfloat16 ha = __float2bfloat16(a), hb = __float2bfloat16(b);
    float ra = a - __bfloat162float(ha);
    float rb = b - __bfloat162float(hb);
    __nv_bfloat16 la = __float2bfloat16(ra), lb = __float2bfloat16(rb);
    hw = ((uint32_t)__bfloat16_as_ushort(hb) << 16) | __bfloat16_as_ushort(ha);
    lw = ((uint32_t)__bfloat16_as_ushort(lb) << 16) | __bfloat16_as_ushort(la);
}
__device__ __forceinline__ void mma16816(float* c, const uint32_t* a,
                                         uint32_t b0, uint32_t b1) {
    asm("mma.sync.aligned.m16n8k16.row.col.f32.bf16.bf16.f32 "
        "{%0,%1,%2,%3}, {%4,%5,%6,%7}, {%8,%9}, {%0,%1,%2,%3};"
        : "+f"(c[0]), "+f"(c[1]), "+f"(c[2]), "+f"(c[3])
        : "r"(a[0]), "r"(a[1]), "r"(a[2]), "r"(a[3]), "r"(b0), "r"(b1));
}
__device__ __forceinline__ void cp_async16(uint32_t smem_dst, const void* gsrc) {
    asm volatile("cp.async.cg.shared.global [%0], [%1], 16;"
                 :: "r"(smem_dst), "l"(gsrc));
}
__device__ __forceinline__ void cp_async_commit_wait_all() {
    asm volatile("cp.async.commit_group;\n\tcp.async.wait_group 0;" ::: "memory");
}
__device__ __forceinline__ uint32_t smem_u32(const void* p) {
    uint32_t a;
    asm("{ .reg .u64 t; cvta.to.shared.u64 t, %1; cvt.u32.u64 %0, t; }" : "=r"(a) : "l"(p));
    return a;
}

// ---------------- prep: weight convert + zero counts/pool + graph bounds ----
__global__ void prep_kernel(const float* w0, const float* w1, const float* w2,
                            const float* w3, const float* w4, const float* w5,
                            const int* __restrict__ batch) {
    int b = blockIdx.x;
    if (b < 24) {
        const float* ws[6] = {w0, w1, w2, w3, w4, w5};
        int widx = b >> 2, part = b & 3;
        const float* w = ws[widx];
        __nv_bfloat16* hb = g_Wthi + widx * DH * DH;
        __nv_bfloat16* lb = g_Wtlo + widx * DH * DH;
        int end = (part + 1) * 4096;
        for (int idx = part * 4096 + threadIdx.x; idx < end; idx += 256) {
            int n = idx >> 7, k = idx & 127;
            float v = w[k * DH + n];
            __nv_bfloat16 hi = __float2bfloat16(v);
            __nv_bfloat16 lo = __float2bfloat16(v - __bfloat162float(hi));
            hb[idx] = hi;
            lb[idx] = lo;
        }
    } else if (b == 24) {
        for (int i = threadIdx.x; i < GG * DH; i += 256) g_pool[i] = 0.0f;
        int g = threadIdx.x;
        if (g <= GG) {
            int lo = 0, hi = NN;
            while (lo < hi) {
                int mid = (lo + hi) >> 1;
                if (batch[mid] < g) lo = mid + 1; else hi = mid;
            }
            g_gstart[g] = lo;
        }
    } else {
        int i = (b - 25) * 1024 + threadIdx.x;
        #pragma unroll
        for (int q = 0; q < 4; q++) {
            int j = i + q * 256;
            if (j < NN) g_counts[j] = 0;
        }
    }
}

__global__ void count_edges(const int* __restrict__ dst) {
    int e = blockIdx.x * blockDim.x + threadIdx.x;
    if (e < EE) atomicAdd(&g_counts[dst[e]], 1);
}

// ---------------- parallel scan (3 stages) ----------------------------------
__global__ void scan_stage1() {
    __shared__ int wsum[32];
    int tid = threadIdx.x, lane = tid & 31, w = tid >> 5;
    int i = blockIdx.x * 1024 + tid;
    int v = (i < NN) ? g_counts[i] : 0;
    int s = v;
    #pragma unroll
    for (int o = 1; o < 32; o <<= 1) s += __shfl_xor_sync(0xffffffffu, s, o);
    if (lane == 0) wsum[w] = s;
    __syncthreads();
    if (w == 0) {
        int t = (lane < 32) ? wsum[lane] : 0;
        #pragma unroll
        for (int o = 1; o < 32; o <<= 1) t += __shfl_xor_sync(0xffffffffu, t, o);
        if (lane == 0) g_bsum[blockIdx.x] = t;
    }
}
__global__ void scan_stage2() {
    int tid = threadIdx.x, lane = tid & 31, w = tid >> 5;
    __shared__ int wsum[4];
    int v = (tid < SCB) ? g_bsum[tid] : 0;
    int incl = v;
    #pragma unroll
    for (int o = 1; o < 32; o <<= 1) {
        int t = __shfl_up_sync(0xffffffffu, incl, o);
        if (lane >= o) incl += t;
    }
    if (lane == 31) wsum[w] = incl;
    __syncthreads();
    int woff = 0;
    #pragma unroll
    for (int q = 0; q < 4; q++) if (q < w) woff += wsum[q];
    if (tid < SCB) g_boff[tid] = woff + incl - v;
    if (tid == SCB - 1) g_rowptr[NN] = woff + incl;
}
__global__ void scan_stage3() {
    __shared__ int wsum[32];
    int tid = threadIdx.x, lane = tid & 31, w = tid >> 5;
    int i = blockIdx.x * 1024 + tid;
    int v = (i < NN) ? g_counts[i] : 0;
    int incl = v;
    #pragma unroll
    for (int o = 1; o < 32; o <<= 1) {
        int t = __shfl_up_sync(0xffffffffu, incl, o);
        if (lane >= o) incl += t;
    }
    if (lane == 31) wsum[w] = incl;
    __syncthreads();
    if (w == 0) {
        int s = wsum[lane];
        #pragma unroll
        for (int o = 1; o < 32; o <<= 1) {
            int t = __shfl_up_sync(0xffffffffu, s, o);
            if (lane >= o) s += t;
        }
        wsum[lane] = s;
    }
    __syncthreads();
    if (i < NN) {
        int woff = (w > 0) ? wsum[w - 1] : 0;
        int excl = g_boff[blockIdx.x] + woff + incl - v;
        g_rowptr[i] = excl;
        g_cur[i] = excl;
    }
}

__global__ void fill_csr(const int* __restrict__ src, const int* __restrict__ dst) {
    int e = blockIdx.x * blockDim.x + threadIdx.x;
    if (e < EE) {
        int p = atomicAdd(&g_cur[dst[e]], 1);
        g_csr_src[p] = src[e];
    }
}

// ---------------- fused layer kernel -----------------------------------------
// Per 128-row tile: gather(hin)+split -> GEMM1(+b1,relu)+split -> GEMM2(+b2)
// BUF 0: x -> g_hA (LN).  BUF 1: g_hA -> g_hB (LN).  BUF 2: g_hB -> out/pool.
// Input and output buffers are always distinct -> no cross-CTA race.
#define SA_HI 0
#define SA_LO 34816
#define S1_HI 69632
#define S1_LO 104448
#define S2_HI 139264
#define S2_LO 174080
#define SEPI  208896
#define SMEM_DYN (208896 + 768 * 4)
#define PITCHW 68   // smem row pitch in 32-bit words (136 bf16)

template <int BUF>
__global__ void __launch_bounds__(256, 1)
layer_kernel(int lidx, const float* __restrict__ xin,
             const float* __restrict__ b1v, const float* __restrict__ b2v,
             const float* __restrict__ lng, const float* __restrict__ lnb,
             float* __restrict__ out) {
    extern __shared__ char smem[];
    uint32_t* sah = (uint32_t*)(smem + SA_HI);
    uint32_t* sal = (uint32_t*)(smem + SA_LO);
    float* rowsum = (float*)(smem + SEPI);   // [0:128)
    float* rowsq  = rowsum + 128;            // [128:256)
    float* sb1    = rowsum + 256;            // [256:384)
    float* sb2    = rowsum + 384;            // [384:512)
    float* slg    = rowsum + 512;            // [512:640)
    float* slb    = rowsum + 640;            // [640:768)

    const float* __restrict__ hin =
        (BUF == 0) ? xin : (BUF == 1) ? (const float*)g_hA : (const float*)g_hB;
    float* __restrict__ hout = (BUF == 0) ? g_hA : g_hB;   // unused for BUF==2

    int tid = threadIdx.x;
    int tile = blockIdx.x;

    // ---- prefetch W1/W2 planes via cp.async ----
    {
        int wA = 2 * lidx, wB = 2 * lidx + 1;
        const char* w1h = (const char*)((const uint32_t*)g_Wthi + wA * 8192);
        const char* w1l = (const char*)((const uint32_t*)g_Wtlo + wA * 8192);
        const char* w2h = (const char*)((const uint32_t*)g_Wthi + wB * 8192);
        const char* w2l = (const char*)((const uint32_t*)g_Wtlo + wB * 8192);
        uint32_t d1h = smem_u32(smem + S1_HI), d1l = smem_u32(smem + S1_LO);
        uint32_t d2h = smem_u32(smem + S2_HI), d2l = smem_u32(smem + S2_LO);
        for (int i = tid; i < 2048; i += 256) {      // 128 rows x 16 chunks of 16B
            int row = i >> 4, c16 = i & 15;
            uint32_t doff = (row * PITCHW + c16 * 4) * 4;
            cp_async16(d1h + doff, w1h + i * 16);
            cp_async16(d1l + doff, w1l + i * 16);
            cp_async16(d2h + doff, w2h + i * 16);
            cp_async16(d2l + doff, w2l + i * 16);
        }
    }
    if (tid < 128) {
        sb1[tid] = b1v[tid];
        sb2[tid] = b2v[tid];
        if (BUF != 2) {
            slg[tid] = lng[tid];
            slb[tid] = lnb[tid];
            rowsum[tid] = 0.0f;
            rowsq[tid] = 0.0f;
        }
    }

    // ---- gather: warp w handles rows w*16..w*16+15; lane covers 4 cols ----
    {
        int w = tid >> 5, lane = tid & 31;
        int off = lane * 4;
        #pragma unroll 1
        for (int i = 0; i < 16; i++) {
            int r = w * 16 + i;
            int n = tile * 128 + r;
            float4 acc = make_float4(0.f, 0.f, 0.f, 0.f);
            if (n < NN) {
                acc = *(const float4*)&hin[(size_t)n * DH + off];
                int p = g_rowptr[n], e = g_rowptr[n + 1];
                for (; p + 4 <= e; p += 4) {
                    int s0 = g_csr_src[p], s1 = g_csr_src[p + 1];
                    int s2 = g_csr_src[p + 2], s3 = g_csr_src[p + 3];
                    float4 v0 = *(const float4*)&hin[(size_t)s0 * DH + off];
                    float4 v1 = *(const float4*)&hin[(size_t)s1 * DH + off];
                    float4 v2 = *(const float4*)&hin[(size_t)s2 * DH + off];
                    float4 v3 = *(const float4*)&hin[(size_t)s3 * DH + off];
                    acc.x += v0.x + v1.x + v2.x + v3.x;
                    acc.y += v0.y + v1.y + v2.y + v3.y;
                    acc.z += v0.z + v1.z + v2.z + v3.z;
                    acc.w += v0.w + v1.w + v2.w + v3.w;
                }
                for (; p < e; ++p) {
                    int s = g_csr_src[p];
                    float4 v = *(const float4*)&hin[(size_t)s * DH + off];
                    acc.x += v.x; acc.y += v.y; acc.z += v.z; acc.w += v.w;
                }
            }
            uint32_t hw0, lw0, hw1, lw1;
            split2(acc.x, acc.y, hw0, lw0);
            split2(acc.z, acc.w, hw1, lw1);
            int idx = r * PITCHW + lane * 2;
            sah[idx] = hw0; sah[idx + 1] = hw1;
            sal[idx] = lw0; sal[idx + 1] = lw1;
        }
    }
    cp_async_commit_wait_all();
    __syncthreads();

    int wid = tid >> 5, lane = tid & 31, g = lane >> 2, t = lane & 3;
    int m0 = (wid >> 1) * 32;       // warp row base (2 m16 tiles)
    int nb = (wid & 1) * 64;        // warp col base (8 n8 tiles)

    float acc[2][8][4];

    // ================= GEMM1 =================
    #pragma unroll
    for (int mi = 0; mi < 2; mi++)
        #pragma unroll
        for (int j = 0; j < 8; j++)
            #pragma unroll
            for (int q = 0; q < 4; q++) acc[mi][j][q] = 0.0f;

    #pragma unroll 1
    for (int pass = 0; pass < 3; pass++) {
        const uint32_t* Ap = (pass == 1) ? sal : sah;
        const uint32_t* Wp = (pass == 2) ? (uint32_t*)(smem + S1_LO)
                                         : (uint32_t*)(smem + S1_HI);
        #pragma unroll
        for (int kk = 0; kk < 8; kk++) {
            int ko = kk * 8 + t;
            uint32_t a[2][4];
            #pragma unroll
            for (int mi = 0; mi < 2; mi++) {
                int r = m0 + mi * 16 + g;
                a[mi][0] = Ap[r * PITCHW + ko];
                a[mi][1] = Ap[(r + 8) * PITCHW + ko];
                a[mi][2] = Ap[r * PITCHW + ko + 4];
                a[mi][3] = Ap[(r + 8) * PITCHW + ko + 4];
            }
            #pragma unroll
            for (int j = 0; j < 8; j++) {
                int n = nb + j * 8 + g;
                uint32_t b0 = Wp[n * PITCHW + ko];
                uint32_t b1 = Wp[n * PITCHW + ko + 4];
                mma16816(acc[0][j], a[0], b0, b1);
                mma16816(acc[1][j], a[1], b0, b1);
            }
        }
    }
    __syncthreads();   // all warps done reading A planes

    // relu(acc + b1), split back into A planes (C1 tile becomes A2 tile)
    #pragma unroll
    for (int mi = 0; mi < 2; mi++) {
        #pragma unroll
        for (int j = 0; j < 8; j++) {
            int c = nb + j * 8 + t * 2;
            float v0 = fmaxf(acc[mi][j][0] + sb1[c], 0.f);
            float v1 = fmaxf(acc[mi][j][1] + sb1[c + 1], 0.f);
            float v2 = fmaxf(acc[mi][j][2] + sb1[c], 0.f);
            float v3 = fmaxf(acc[mi][j][3] + sb1[c + 1], 0.f);
            uint32_t hw, lw;
            int r0 = m0 + mi * 16 + g;
            int wc = (nb >> 1) + j * 4 + t;
            split2(v0, v1, hw, lw);
            sah[r0 * PITCHW + wc] = hw;
            sal[r0 * PITCHW + wc] = lw;
            split2(v2, v3, hw, lw);
            sah[(r0 + 8) * PITCHW + wc] = hw;
            sal[(r0 + 8) * PITCHW + wc] = lw;
        }
    }
    __syncthreads();

    // ================= GEMM2 =================
    #pragma unroll
    for (int mi = 0; mi < 2; mi++)
        #pragma unroll
        for (int j = 0; j < 8; j++)
            #pragma unroll
            for (int q = 0; q < 4; q++) acc[mi][j][q] = 0.0f;

    #pragma unroll 1
    for (int pass = 0; pass < 3; pass++) {
        const uint32_t* Ap = (pass == 1) ? sal : sah;
        const uint32_t* Wp = (pass == 2) ? (uint32_t*)(smem + S2_LO)
                                         : (uint32_t*)(smem + S2_HI);
        #pragma unroll
        for (int kk = 0; kk < 8; kk++) {
            int ko = kk * 8 + t;
            uint32_t a[2][4];
            #pragma unroll
            for (int mi = 0; mi < 2; mi++) {
                int r = m0 + mi * 16 + g;
                a[mi][0] = Ap[r * PITCHW + ko];
                a[mi][1] = Ap[(r + 8) * PITCHW + ko];
                a[mi][2] = Ap[r * PITCHW + ko + 4];
                a[mi][3] = Ap[(r + 8) * PITCHW + ko + 4];
            }
            #pragma unroll
            for (int j = 0; j < 8; j++) {
                int n = nb + j * 8 + g;
                uint32_t b0 = Wp[n * PITCHW + ko];
                uint32_t b1 = Wp[n * PITCHW + ko + 4];
                mma16816(acc[0][j], a[0], b0, b1);
                mma16816(acc[1][j], a[1], b0, b1);
            }
        }
    }

    // ---- epilogue ----
    if (BUF != 2) {
        float s[2][2], q[2][2];
        #pragma unroll
        for (int mi = 0; mi < 2; mi++) { s[mi][0]=s[mi][1]=q[mi][0]=q[mi][1]=0.f; }
        #pragma unroll
        for (int mi = 0; mi < 2; mi++)
            #pragma unroll
            for (int j = 0; j < 8; j++) {
                int c = nb + j * 8 + t * 2;
                float v0 = fmaxf(acc[mi][j][0] + sb2[c], 0.f);
                float v1 = fmaxf(acc[mi][j][1] + sb2[c + 1], 0.f);
                float v2 = fmaxf(acc[mi][j][2] + sb2[c], 0.f);
                float v3 = fmaxf(acc[mi][j][3] + sb2[c + 1], 0.f);
                acc[mi][j][0] = v0; acc[mi][j][1] = v1;
                acc[mi][j][2] = v2; acc[mi][j][3] = v3;
                s[mi][0] += v0 + v1;  q[mi][0] += v0 * v0 + v1 * v1;
                s[mi][1] += v2 + v3;  q[mi][1] += v2 * v2 + v3 * v3;
            }
        #pragma unroll
        for (int mi = 0; mi < 2; mi++)
            #pragma unroll
            for (int rh = 0; rh < 2; rh++) {
                float ss = s[mi][rh], qq = q[mi][rh];
                ss += __shfl_xor_sync(0xffffffffu, ss, 1);
                qq += __shfl_xor_sync(0xffffffffu, qq, 1);
                ss += __shfl_xor_sync(0xffffffffu, ss, 2);
                qq += __shfl_xor_sync(0xffffffffu, qq, 2);
                if (t == 0) {
                    int rl = m0 + mi * 16 + rh * 8 + g;
                    atomicAdd(&rowsum[rl], ss);
                    atomicAdd(&rowsq[rl], qq);
                }
            }
        __syncthreads();
        if (tid < 128) {
            float mean = rowsum[tid] * (1.0f / DH);
            float var = rowsq[tid] * (1.0f / DH) - mean * mean;
            rowsum[tid] = mean;
            rowsq[tid] = rsqrtf(var + 1e-5f);
        }
        __syncthreads();
        #pragma unroll
        for (int mi = 0; mi < 2; mi++)
            #pragma unroll
            for (int rh = 0; rh < 2; rh++) {
                int rl = m0 + mi * 16 + rh * 8 + g;
                float mean = rowsum[rl], rs = rowsq[rl];
                size_t row = (size_t)tile * 128 + rl;
                #pragma unroll
                for (int j = 0; j < 8; j++) {
                    int c = nb + j * 8 + t * 2;
                    float v0 = acc[mi][j][rh * 2];
                    float v1 = acc[mi][j][rh * 2 + 1];
                    float2 o;
                    o.x = (v0 - mean) * rs * slg[c] + slb[c];
                    o.y = (v1 - mean) * rs * slg[c + 1] + slb[c + 1];
                    *(float2*)&hout[row * DH + c] = o;
                }
            }
    } else {
        #pragma unroll
        for (int mi = 0; mi < 2; mi++)
            #pragma unroll
            for (int rh = 0; rh < 2; rh++) {
                size_t row = (size_t)tile * 128 + m0 + mi * 16 + rh * 8 + g;
                if (row < NN) {
                    #pragma unroll
                    for (int j = 0; j < 8; j++) {
                        int c = nb + j * 8 + t * 2;
                        float2 u;
                        u.x = acc[mi][j][rh * 2] + sb2[c];
                        u.y = acc[mi][j][rh * 2 + 1] + sb2[c + 1];
                        *(float2*)&out[row * DH + c] = u;
                        u.x = fmaxf(u.x, 0.f);
                        u.y = fmaxf(u.y, 0.f);
                        *(float2*)&g_hpool[row * DH + c] = u;
                    }
                }
            }
    }
}

// ---------------- pooling + head --------------------------------------------
__global__ void pool_partial() {
    int g = blockIdx.x;
    int chunk = blockIdx.y;
    int f = threadIdx.x;
    int s = g_gstart[g], e = g_gstart[g + 1];
    int len = e - s;
    int per = (len + (int)gridDim.y - 1) / (int)gridDim.y;
    int a = s + chunk * per;
    int b = min(a + per, e);
    float sum = 0.f;
    for (int n = a; n < b; n++) sum += g_hpool[(size_t)n * DH + f];
    if (a < b) atomicAdd(&g_pool[g * DH + f], sum);
}

__global__ void head_mlp(const float* __restrict__ pw1, const float* __restrict__ pb1,
                         const float* __restrict__ pw2, const float* __restrict__ pb2,
                         float* __restrict__ out) {
    __shared__ float sp[DH];
    __shared__ float sz[DH];
    __shared__ float sl[CC];
    int g = blockIdx.x;
    int f = threadIdx.x;
    float cnt = fmaxf((float)(g_gstart[g + 1] - g_gstart[g]), 1.0f);
    sp[f] = g_pool[g * DH + f] / cnt;
    __syncthreads();
    float z = pb1[f];
    #pragma unroll 8
    for (int k = 0; k < DH; k++) z += sp[k] * pw1[k * DH + f];
    sz[f] = z;
    __syncthreads();
    if (f < CC) {
        float l = pb2[f];
        #pragma unroll 8
        for (int k = 0; k < DH; k++) l += sz[k] * pw2[k * CC + f];
        sl[f] = l;
    }
    __syncthreads();
    if (f < CC) {
        float m = -1e30f;
        #pragma unroll
        for (int c = 0; c < CC; c++) m = fmaxf(m, sl[c]);
        float s = 0.f;
        #pragma unroll
        for (int c = 0; c < CC; c++) s += expf(sl[c] - m);
        out[(size_t)NN * DH + g * CC + f] = sl[f] - m - logf(s);
    }
}

// ---------------- launch ----------------------------------------------------
extern "C" void kernel_launch(void* const* d_in, const int* in_sizes, int n_in,
                              void* d_out, int out_size) {
    const float* x    = (const float*)d_in[0];
    const int* eidx   = (const int*)d_in[1];
    const int* batch  = (const int*)d_in[2];
    const float* w1[3] = {(const float*)d_in[3], (const float*)d_in[7], (const float*)d_in[11]};
    const float* b1[3] = {(const float*)d_in[4], (const float*)d_in[8], (const float*)d_in[12]};
    const float* w2[3] = {(const float*)d_in[5], (const float*)d_in[9], (const float*)d_in[13]};
    const float* b2[3] = {(const float*)d_in[6], (const float*)d_in[10], (const float*)d_in[14]};
    const float* ln_g[2] = {(const float*)d_in[15], (const float*)d_in[17]};
    const float* ln_b[2] = {(const float*)d_in[16], (const float*)d_in[18]};
    const float* pw1 = (const float*)d_in[19];
    const float* pb1 = (const float*)d_in[20];
    const float* pw2 = (const float*)d_in[21];
    const float* pb2 = (const float*)d_in[22];
    float* out = (float*)d_out;

    cudaFuncSetAttribute((const void*)layer_kernel<0>,
                         cudaFuncAttributeMaxDynamicSharedMemorySize, SMEM_DYN);
    cudaFuncSetAttribute((const void*)layer_kernel<1>,
                         cudaFuncAttributeMaxDynamicSharedMemorySize, SMEM_DYN);
    cudaFuncSetAttribute((const void*)layer_kernel<2>,
                         cudaFuncAttributeMaxDynamicSharedMemorySize, SMEM_DYN);

    const int* src = eidx;
    const int* dst = eidx + EE;

    prep_kernel<<<25 + SCB, 256>>>(w1[0], w2[0], w1[1], w2[1], w1[2], w2[2], batch);
    count_edges<<<(EE + 255) / 256, 256>>>(dst);
    scan_stage1<<<SCB, 1024>>>();
    scan_stage2<<<1, 128>>>();
    scan_stage3<<<SCB, 1024>>>();
    fill_csr<<<(EE + 255) / 256, 256>>>(src, dst);

    // ping-pong: x -> g_hA -> g_hB -> out (input/output always distinct)
    layer_kernel<0><<<NT, 256, SMEM_DYN>>>(0, x, b1[0], b2[0], ln_g[0], ln_b[0], nullptr);
    layer_kernel<1><<<NT, 256, SMEM_DYN>>>(1, nullptr, b1[1], b2[1], ln_g[1], ln_b[1], nullptr);
    layer_kernel<2><<<NT, 256, SMEM_DYN>>>(2, nullptr, b1[2], b2[2], nullptr, nullptr, out);

    pool_partial<<<dim3(GG, 16), DH>>>();
    head_mlp<<<GG, DH>>>(pw1, pb1, pw2, pb2, out);
}

// round 16
// speedup vs baseline: 1.5766x; 1.5766x over previous
#include <cuda_runtime.h>
#include <cuda_bf16.h>
#include <math.h>
#include <stdint.h>

#define NN 100000
#define EE 1600000
#define DH 128
#define GG 64
#define CC 10
#define NT 782               // ceil(NN/128)
#define NPAD (NT * 128)      // 100096
#define SCB 98               // scan blocks: ceil(NN/1024)

// ---------------- scratch (static device arrays; allocation forbidden) ------
__device__ float g_t[NPAD * DH];       // gather output (MLP input); rows>=NN stay 0
__device__ float g_h[NPAD * DH];       // layer output / next gather input
__device__ float g_hpool[NPAD * DH];   // relu(u) after layer 2 for pooling
__device__ __nv_bfloat16 g_Wthi[6 * DH * DH];  // weights transposed [n][k], bf16 hi
__device__ __nv_bfloat16 g_Wtlo[6 * DH * DH];  // bf16 lo plane
__device__ int   g_counts[NN];
__device__ int   g_rowptr[NN + 1];
__device__ int   g_cur[NN];
__device__ int   g_csr_src[EE];
__device__ int   g_bsum[SCB];
__device__ int   g_boff[SCB];
__device__ int   g_gstart[GG + 1];
__device__ float g_pool[GG * DH];

// ---------------- helpers ----------------------------------------------------
__device__ __forceinline__ void split2(float a, float b, uint32_t& hw, uint32_t& lw) {
    __nv_bfloat16 ha = __float2bfloat16(a), hb = __float2bfloat16(b);
    float ra = a - __bfloat162float(ha);
    float rb = b - __bfloat162float(hb);
    __nv_bfloat16 la = __float2bfloat16(ra), lb = __float2bfloat16(rb);
    hw = ((uint32_t)__bfloat16_as_ushort(hb) << 16) | __bfloat16_as_ushort(ha);
    lw = ((uint32_t)__bfloat16_as_ushort(lb) << 16) | __bfloat16_as_ushort(la);
}
__device__ __forceinline__ void mma16816(float* c, const uint32_t* a,
                                         uint32_t b0, uint32_t b1) {
    asm("mma.sync.aligned.m16n8k16.row.col.f32.bf16.bf16.f32 "
        "{%0,%1,%2,%3}, {%4,%5,%6,%7}, {%8,%9}, {%0,%1,%2,%3};"
        : "+f"(c[0]), "+f"(c[1]), "+f"(c[2]), "+f"(c[3])
        : "r"(a[0]), "r"(a[1]), "r"(a[2]), "r"(a[3]), "r"(b0), "r"(b1));
}
__device__ __forceinline__ void cp_async16(uint32_t smem_dst, const void* gsrc) {
    asm volatile("cp.async.cg.shared.global [%0], [%1], 16;"
                 :: "r"(smem_dst), "l"(gsrc));
}
__device__ __forceinline__ void cp_async_commit_wait_all() {
    asm volatile("cp.async.commit_group;\n\tcp.async.wait_group 0;" ::: "memory");
}
__device__ __forceinline__ uint32_t smem_u32(const void* p) {
    uint32_t a;
    asm("{ .reg .u64 t; cvta.to.shared.u64 t, %1; cvt.u32.u64 %0, t; }" : "=r"(a) : "l"(p));
    return a;
}

// ---------------- prep: weight convert + zero counts/pool + graph bounds ----
__global__ void prep_kernel(const float* w0, const float* w1, const float* w2,
                            const float* w3, const float* w4, const float* w5,
                            const int* __restrict__ batch) {
    int b = blockIdx.x;
    if (b < 24) {
        const float* ws[6] = {w0, w1, w2, w3, w4, w5};
        int widx = b >> 2, part = b & 3;
        const float* w = ws[widx];
        __nv_bfloat16* hb = g_Wthi + widx * DH * DH;
        __nv_bfloat16* lb = g_Wtlo + widx * DH * DH;
        int end = (part + 1) * 4096;
        for (int idx = part * 4096 + threadIdx.x; idx < end; idx += 256) {
            int n = idx >> 7, k = idx & 127;
            float v = w[k * DH + n];
            __nv_bfloat16 hi = __float2bfloat16(v);
            __nv_bfloat16 lo = __float2bfloat16(v - __bfloat162float(hi));
            hb[idx] = hi;
            lb[idx] = lo;
        }
    } else if (b == 24) {
        for (int i = threadIdx.x; i < GG * DH; i += 256) g_pool[i] = 0.0f;
        int g = threadIdx.x;
        if (g <= GG) {
            int lo = 0, hi = NN;
            while (lo < hi) {
                int mid = (lo + hi) >> 1;
                if (batch[mid] < g) lo = mid + 1; else hi = mid;
            }
            g_gstart[g] = lo;
        }
    } else {
        int i = (b - 25) * 1024 + threadIdx.x;
        #pragma unroll
        for (int q = 0; q < 4; q++) {
            int j = i + q * 256;
            if (j < NN) g_counts[j] = 0;
        }
    }
}

__global__ void count_edges(const int* __restrict__ dst) {
    int e = blockIdx.x * blockDim.x + threadIdx.x;
    if (e < EE) atomicAdd(&g_counts[dst[e]], 1);
}

// ---------------- parallel scan (3 stages) ----------------------------------
__global__ void scan_stage1() {
    __shared__ int wsum[32];
    int tid = threadIdx.x, lane = tid & 31, w = tid >> 5;
    int i = blockIdx.x * 1024 + tid;
    int v = (i < NN) ? g_counts[i] : 0;
    int s = v;
    #pragma unroll
    for (int o = 1; o < 32; o <<= 1) s += __shfl_xor_sync(0xffffffffu, s, o);
    if (lane == 0) wsum[w] = s;
    __syncthreads();
    if (w == 0) {
        int t = (lane < 32) ? wsum[lane] : 0;
        #pragma unroll
        for (int o = 1; o < 32; o <<= 1) t += __shfl_xor_sync(0xffffffffu, t, o);
        if (lane == 0) g_bsum[blockIdx.x] = t;
    }
}
__global__ void scan_stage2() {
    int tid = threadIdx.x, lane = tid & 31, w = tid >> 5;
    __shared__ int wsum[4];
    int v = (tid < SCB) ? g_bsum[tid] : 0;
    int incl = v;
    #pragma unroll
    for (int o = 1; o < 32; o <<= 1) {
        int t = __shfl_up_sync(0xffffffffu, incl, o);
        if (lane >= o) incl += t;
    }
    if (lane == 31) wsum[w] = incl;
    __syncthreads();
    int woff = 0;
    #pragma unroll
    for (int q = 0; q < 4; q++) if (q < w) woff += wsum[q];
    if (tid < SCB) g_boff[tid] = woff + incl - v;
    if (tid == SCB - 1) g_rowptr[NN] = woff + incl;
}
__global__ void scan_stage3() {
    __shared__ int wsum[32];
    int tid = threadIdx.x, lane = tid & 31, w = tid >> 5;
    int i = blockIdx.x * 1024 + tid;
    int v = (i < NN) ? g_counts[i] : 0;
    int incl = v;
    #pragma unroll
    for (int o = 1; o < 32; o <<= 1) {
        int t = __shfl_up_sync(0xffffffffu, incl, o);
        if (lane >= o) incl += t;
    }
    if (lane == 31) wsum[w] = incl;
    __syncthreads();
    if (w == 0) {
        int s = wsum[lane];
        #pragma unroll
        for (int o = 1; o < 32; o <<= 1) {
            int t = __shfl_up_sync(0xffffffffu, s, o);
            if (lane >= o) s += t;
        }
        wsum[lane] = s;
    }
    __syncthreads();
    if (i < NN) {
        int woff = (w > 0) ? wsum[w - 1] : 0;
        int excl = g_boff[blockIdx.x] + woff + incl - v;
        g_rowptr[i] = excl;
        g_cur[i] = excl;
    }
}

__global__ void fill_csr(const int* __restrict__ src, const int* __restrict__ dst) {
    int e = blockIdx.x * blockDim.x + threadIdx.x;
    if (e < EE) {
        int p = atomicAdd(&g_cur[dst[e]], 1);
        g_csr_src[p] = src[e];
    }
}

// ---------------- gather (separate launch, high occupancy) ------------------
// t[n] = h[n] + sum_{src in CSR(n)} h[src]
template <bool FIRST>
__global__ void gather_kernel(const float* __restrict__ x) {
    const float* __restrict__ h = FIRST ? x : (const float*)g_h;
    int warp = threadIdx.x >> 5, lane = threadIdx.x & 31;
    int n = blockIdx.x * 8 + warp;
    if (n >= NN) return;
    int off = lane * 4;
    float4 acc = *(const float4*)&h[(size_t)n * DH + off];
    int p = g_rowptr[n], e = g_rowptr[n + 1];
    for (; p + 4 <= e; p += 4) {
        int s0 = g_csr_src[p], s1 = g_csr_src[p + 1];
        int s2 = g_csr_src[p + 2], s3 = g_csr_src[p + 3];
        float4 v0 = *(const float4*)&h[(size_t)s0 * DH + off];
        float4 v1 = *(const float4*)&h[(size_t)s1 * DH + off];
        float4 v2 = *(const float4*)&h[(size_t)s2 * DH + off];
        float4 v3 = *(const float4*)&h[(size_t)s3 * DH + off];
        acc.x += v0.x + v1.x + v2.x + v3.x;
        acc.y += v0.y + v1.y + v2.y + v3.y;
        acc.z += v0.z + v1.z + v2.z + v3.z;
        acc.w += v0.w + v1.w + v2.w + v3.w;
    }
    for (; p < e; ++p) {
        int s = g_csr_src[p];
        float4 v = *(const float4*)&h[(size_t)s * DH + off];
        acc.x += v.x; acc.y += v.y; acc.z += v.z; acc.w += v.w;
    }
    *(float4*)&g_t[(size_t)n * DH + off] = acc;
}

// ---------------- fused MLP kernel (GEMM1 + relu + GEMM2 + epilogue) --------
// A = g_t tile (fp32 -> bf16 hi/lo in smem), W1/W2 prefetched via cp.async.
// VAR 0: LN epilogue -> g_h.   VAR 1: emb -> out, relu -> g_hpool.
#define SA_HI 0
#define SA_LO 34816
#define S1_HI 69632
#define S1_LO 104448
#define S2_HI 139264
#define S2_LO 174080
#define SEPI  208896
#define SMEM_DYN (208896 + 768 * 4)
#define PITCHW 68   // smem row pitch in 32-bit words (136 bf16)

template <int VAR>
__global__ void __launch_bounds__(256, 1)
mlp_kernel(int lidx,
           const float* __restrict__ b1v, const float* __restrict__ b2v,
           const float* __restrict__ lng, const float* __restrict__ lnb,
           float* __restrict__ out) {
    extern __shared__ char smem[];
    uint32_t* sah = (uint32_t*)(smem + SA_HI);
    uint32_t* sal = (uint32_t*)(smem + SA_LO);
    float* rowsum = (float*)(smem + SEPI);   // [0:128)
    float* rowsq  = rowsum + 128;            // [128:256)
    float* sb1    = rowsum + 256;            // [256:384)
    float* sb2    = rowsum + 384;            // [384:512)
    float* slg    = rowsum + 512;            // [512:640)
    float* slb    = rowsum + 640;            // [640:768)

    int tid = threadIdx.x;
    int tile = blockIdx.x;

    // ---- prefetch W1/W2 planes via cp.async ----
    {
        int wA = 2 * lidx, wB = 2 * lidx + 1;
        const char* w1h = (const char*)((const uint32_t*)g_Wthi + wA * 8192);
        const char* w1l = (const char*)((const uint32_t*)g_Wtlo + wA * 8192);
        const char* w2h = (const char*)((const uint32_t*)g_Wthi + wB * 8192);
        const char* w2l = (const char*)((const uint32_t*)g_Wtlo + wB * 8192);
        uint32_t d1h = smem_u32(smem + S1_HI), d1l = smem_u32(smem + S1_LO);
        uint32_t d2h = smem_u32(smem + S2_HI), d2l = smem_u32(smem + S2_LO);
        for (int i = tid; i < 2048; i += 256) {      // 128 rows x 16 chunks of 16B
            int row = i >> 4, c16 = i & 15;
            uint32_t doff = (row * PITCHW + c16 * 4) * 4;
            cp_async16(d1h + doff, w1h + i * 16);
            cp_async16(d1l + doff, w1l + i * 16);
            cp_async16(d2h + doff, w2h + i * 16);
            cp_async16(d2l + doff, w2l + i * 16);
        }
    }
    // ---- load A tile (fp32 -> bf16 hi/lo planes); rows >= NN are zeros ----
    {
        const float* Asrc = (const float*)g_t + (size_t)tile * 128 * DH;
        #pragma unroll
        for (int q = 0; q < 16; q++) {               // 4096 float4s / 256 threads
            int i = q * 256 + tid;
            int row = i >> 5, c4 = (i & 31) * 4;
            float4 v = *(const float4*)(Asrc + row * DH + c4);
            uint32_t hw0, lw0, hw1, lw1;
            split2(v.x, v.y, hw0, lw0);
            split2(v.z, v.w, hw1, lw1);
            int w = row * PITCHW + (c4 >> 1);
            sah[w] = hw0; sah[w + 1] = hw1;
            sal[w] = lw0; sal[w + 1] = lw1;
        }
        if (tid < 128) {
            sb1[tid] = b1v[tid];
            sb2[tid] = b2v[tid];
            if (VAR == 0) {
                slg[tid] = lng[tid];
                slb[tid] = lnb[tid];
                rowsum[tid] = 0.0f;
                rowsq[tid] = 0.0f;
            }
        }
    }
    cp_async_commit_wait_all();
    __syncthreads();

    int wid = tid >> 5, lane = tid & 31, g = lane >> 2, t = lane & 3;
    int m0 = (wid >> 1) * 32;       // warp row base (2 m16 tiles)
    int nb = (wid & 1) * 64;        // warp col base (8 n8 tiles)

    float acc[2][8][4];

    // ================= GEMM1 =================
    #pragma unroll
    for (int mi = 0; mi < 2; mi++)
        #pragma unroll
        for (int j = 0; j < 8; j++)
            #pragma unroll
            for (int q = 0; q < 4; q++) acc[mi][j][q] = 0.0f;

    #pragma unroll 1
    for (int pass = 0; pass < 3; pass++) {
        const uint32_t* Ap = (pass == 1) ? sal : sah;
        const uint32_t* Wp = (pass == 2) ? (uint32_t*)(smem + S1_LO)
                                         : (uint32_t*)(smem + S1_HI);
        #pragma unroll
        for (int kk = 0; kk < 8; kk++) {
            int ko = kk * 8 + t;
            uint32_t a[2][4];
            #pragma unroll
            for (int mi = 0; mi < 2; mi++) {
                int r = m0 + mi * 16 + g;
                a[mi][0] = Ap[r * PITCHW + ko];
                a[mi][1] = Ap[(r + 8) * PITCHW + ko];
                a[mi][2] = Ap[r * PITCHW + ko + 4];
                a[mi][3] = Ap[(r + 8) * PITCHW + ko + 4];
            }
            #pragma unroll
            for (int j = 0; j < 8; j++) {
                int n = nb + j * 8 + g;
                uint32_t b0 = Wp[n * PITCHW + ko];
                uint32_t b1 = Wp[n * PITCHW + ko + 4];
                mma16816(acc[0][j], a[0], b0, b1);
                mma16816(acc[1][j], a[1], b0, b1);
            }
        }
    }
    __syncthreads();   // all warps done reading A planes

    // relu(acc + b1), split back into A planes (C1 tile becomes A2 tile)
    #pragma unroll
    for (int mi = 0; mi < 2; mi++) {
        #pragma unroll
        for (int j = 0; j < 8; j++) {
            int c = nb + j * 8 + t * 2;
            float v0 = fmaxf(acc[mi][j][0] + sb1[c], 0.f);
            float v1 = fmaxf(acc[mi][j][1] + sb1[c + 1], 0.f);
            float v2 = fmaxf(acc[mi][j][2] + sb1[c], 0.f);
            float v3 = fmaxf(acc[mi][j][3] + sb1[c + 1], 0.f);
            uint32_t hw, lw;
            int r0 = m0 + mi * 16 + g;
            int wc = (nb >> 1) + j * 4 + t;
            split2(v0, v1, hw, lw);
            sah[r0 * PITCHW + wc] = hw;
            sal[r0 * PITCHW + wc] = lw;
            split2(v2, v3, hw, lw);
            sah[(r0 + 8) * PITCHW + wc] = hw;
            sal[(r0 + 8) * PITCHW + wc] = lw;
        }
    }
    __syncthreads();

    // ================= GEMM2 =================
    #pragma unroll
    for (int mi = 0; mi < 2; mi++)
        #pragma unroll
        for (int j = 0; j < 8; j++)
            #pragma unroll
            for (int q = 0; q < 4; q++) acc[mi][j][q] = 0.0f;

    #pragma unroll 1
    for (int pass = 0; pass < 3; pass++) {
        const uint32_t* Ap = (pass == 1) ? sal : sah;
        const uint32_t* Wp = (pass == 2) ? (uint32_t*)(smem + S2_LO)
                                         : (uint32_t*)(smem + S2_HI);
        #pragma unroll
        for (int kk = 0; kk < 8; kk++) {
            int ko = kk * 8 + t;
            uint32_t a[2][4];
            #pragma unroll
            for (int mi = 0; mi < 2; mi++) {
                int r = m0 + mi * 16 + g;
                a[mi][0] = Ap[r * PITCHW + ko];
                a[mi][1] = Ap[(r + 8) * PITCHW + ko];
                a[mi][2] = Ap[r * PITCHW + ko + 4];
                a[mi][3] = Ap[(r + 8) * PITCHW + ko + 4];
            }
            #pragma unroll
            for (int j = 0; j < 8; j++) {
                int n = nb + j * 8 + g;
                uint32_t b0 = Wp[n * PITCHW + ko];
                uint32_t b1 = Wp[n * PITCHW + ko + 4];
                mma16816(acc[0][j], a[0], b0, b1);
                mma16816(acc[1][j], a[1], b0, b1);
            }
        }
    }

    // ---- epilogue ----
    if (VAR == 0) {
        float s[2][2], q[2][2];
        #pragma unroll
        for (int mi = 0; mi < 2; mi++) { s[mi][0]=s[mi][1]=q[mi][0]=q[mi][1]=0.f; }
        #pragma unroll
        for (int mi = 0; mi < 2; mi++)
            #pragma unroll
            for (int j = 0; j < 8; j++) {
                int c = nb + j * 8 + t * 2;
                float v0 = fmaxf(acc[mi][j][0] + sb2[c], 0.f);
                float v1 = fmaxf(acc[mi][j][1] + sb2[c + 1], 0.f);
                float v2 = fmaxf(acc[mi][j][2] + sb2[c], 0.f);
                float v3 = fmaxf(acc[mi][j][3] + sb2[c + 1], 0.f);
                acc[mi][j][0] = v0; acc[mi][j][1] = v1;
                acc[mi][j][2] = v2; acc[mi][j][3] = v3;
                s[mi][0] += v0 + v1;  q[mi][0] += v0 * v0 + v1 * v1;
                s[mi][1] += v2 + v3;  q[mi][1] += v2 * v2 + v3 * v3;
            }
        #pragma unroll
        for (int mi = 0; mi < 2; mi++)
            #pragma unroll
            for (int rh = 0; rh < 2; rh++) {
                float ss = s[mi][rh], qq = q[mi][rh];
                ss += __shfl_xor_sync(0xffffffffu, ss, 1);
                qq += __shfl_xor_sync(0xffffffffu, qq, 1);
                ss += __shfl_xor_sync(0xffffffffu, ss, 2);
                qq += __shfl_xor_sync(0xffffffffu, qq, 2);
                if (t == 0) {
                    int rl = m0 + mi * 16 + rh * 8 + g;
                    atomicAdd(&rowsum[rl], ss);
                    atomicAdd(&rowsq[rl], qq);
                }
            }
        __syncthreads();
        if (tid < 128) {
            float mean = rowsum[tid] * (1.0f / DH);
            float var = rowsq[tid] * (1.0f / DH) - mean * mean;
            rowsum[tid] = mean;
            rowsq[tid] = rsqrtf(var + 1e-5f);
        }
        __syncthreads();
        #pragma unroll
        for (int mi = 0; mi < 2; mi++)
            #pragma unroll
            for (int rh = 0; rh < 2; rh++) {
                int rl = m0 + mi * 16 + rh * 8 + g;
                float mean = rowsum[rl], rs = rowsq[rl];
                size_t row = (size_t)tile * 128 + rl;
                #pragma unroll
                for (int j = 0; j < 8; j++) {
                    int c = nb + j * 8 + t * 2;
                    float v0 = acc[mi][j][rh * 2];
                    float v1 = acc[mi][j][rh * 2 + 1];
                    float2 o;
                    o.x = (v0 - mean) * rs * slg[c] + slb[c];
                    o.y = (v1 - mean) * rs * slg[c + 1] + slb[c + 1];
                    *(float2*)&g_h[row * DH + c] = o;
                }
            }
    } else {
        #pragma unroll
        for (int mi = 0; mi < 2; mi++)
            #pragma unroll
            for (int rh = 0; rh < 2; rh++) {
                size_t row = (size_t)tile * 128 + m0 + mi * 16 + rh * 8 + g;
                if (row < NN) {
                    #pragma unroll
                    for (int j = 0; j < 8; j++) {
                        int c = nb + j * 8 + t * 2;
                        float2 u;
                        u.x = acc[mi][j][rh * 2] + sb2[c];
                        u.y = acc[mi][j][rh * 2 + 1] + sb2[c + 1];
                        *(float2*)&out[row * DH + c] = u;
                        u.x = fmaxf(u.x, 0.f);
                        u.y = fmaxf(u.y, 0.f);
                        *(float2*)&g_hpool[row * DH + c] = u;
                    }
                }
            }
    }
}

// ---------------- pooling + head --------------------------------------------
__global__ void pool_partial() {
    int g = blockIdx.x;
    int chunk = blockIdx.y;
    int f = threadIdx.x;
    int s = g_gstart[g], e = g_gstart[g + 1];
    int len = e - s;
    int per = (len + (int)gridDim.y - 1) / (int)gridDim.y;
    int a = s + chunk * per;
    int b = min(a + per, e);
    float sum = 0.f;
    for (int n = a; n < b; n++) sum += g_hpool[(size_t)n * DH + f];
    if (a < b) atomicAdd(&g_pool[g * DH + f], sum);
}

__global__ void head_mlp(const float* __restrict__ pw1, const float* __restrict__ pb1,
                         const float* __restrict__ pw2, const float* __restrict__ pb2,
                         float* __restrict__ out) {
    __shared__ float sp[DH];
    __shared__ float sz[DH];
    __shared__ float sl[CC];
    int g = blockIdx.x;
    int f = threadIdx.x;
    float cnt = fmaxf((float)(g_gstart[g + 1] - g_gstart[g]), 1.0f);
    sp[f] = g_pool[g * DH + f] / cnt;
    __syncthreads();
    float z = pb1[f];
    #pragma unroll 8
    for (int k = 0; k < DH; k++) z += sp[k] * pw1[k * DH + f];
    sz[f] = z;
    __syncthreads();
    if (f < CC) {
        float l = pb2[f];
        #pragma unroll 8
        for (int k = 0; k < DH; k++) l += sz[k] * pw2[k * CC + f];
        sl[f] = l;
    }
    __syncthreads();
    if (f < CC) {
        float m = -1e30f;
        #pragma unroll
        for (int c = 0; c < CC; c++) m = fmaxf(m, sl[c]);
        float s = 0.f;
        #pragma unroll
        for (int c = 0; c < CC; c++) s += expf(sl[c] - m);
        out[(size_t)NN * DH + g * CC + f] = sl[f] - m - logf(s);
    }
}

// ---------------- launch ----------------------------------------------------
extern "C" void kernel_launch(void* const* d_in, const int* in_sizes, int n_in,
                              void* d_out, int out_size) {
    const float* x    = (const float*)d_in[0];
    const int* eidx   = (const int*)d_in[1];
    const int* batch  = (const int*)d_in[2];
    const float* w1[3] = {(const float*)d_in[3], (const float*)d_in[7], (const float*)d_in[11]};
    const float* b1[3] = {(const float*)d_in[4], (const float*)d_in[8], (const float*)d_in[12]};
    const float* w2[3] = {(const float*)d_in[5], (const float*)d_in[9], (const float*)d_in[13]};
    const float* b2[3] = {(const float*)d_in[6], (const float*)d_in[10], (const float*)d_in[14]};
    const float* ln_g[2] = {(const float*)d_in[15], (const float*)d_in[17]};
    const float* ln_b[2] = {(const float*)d_in[16], (const float*)d_in[18]};
    const float* pw1 = (const float*)d_in[19];
    const float* pb1 = (const float*)d_in[20];
    const float* pw2 = (const float*)d_in[21];
    const float* pb2 = (const float*)d_in[22];
    float* out = (float*)d_out;

    cudaFuncSetAttribute((const void*)mlp_kernel<0>,
                         cudaFuncAttributeMaxDynamicSharedMemorySize, SMEM_DYN);
    cudaFuncSetAttribute((const void*)mlp_kernel<1>,
                         cudaFuncAttributeMaxDynamicSharedMemorySize, SMEM_DYN);

    const int* src = eidx;
    const int* dst = eidx + EE;

    prep_kernel<<<25 + SCB, 256>>>(w1[0], w2[0], w1[1], w2[1], w1[2], w2[2], batch);
    count_edges<<<(EE + 255) / 256, 256>>>(dst);
    scan_stage1<<<SCB, 1024>>>();
    scan_stage2<<<1, 128>>>();
    scan_stage3<<<SCB, 1024>>>();
    fill_csr<<<(EE + 255) / 256, 256>>>(src, dst);

    const int node_blocks = (NN + 7) / 8;

    for (int L = 0; L < 3; L++) {
        if (L == 0) gather_kernel<true><<<node_blocks, 256>>>(x);
        else        gather_kernel<false><<<node_blocks, 256>>>(nullptr);
        if (L < 2)
            mlp_kernel<0><<<NT, 256, SMEM_DYN>>>(L, b1[L], b2[L], ln_g[L], ln_b[L], nullptr);
        else
            mlp_kernel<1><<<NT, 256, SMEM_DYN>>>(L, b1[L], b2[L], nullptr, nullptr, out);
    }

    pool_partial<<<dim3(GG, 16), DH>>>();
    head_mlp<<<GG, DH>>>(pw1, pb1, pw2, pb2, out);
}

// round 17
// speedup vs baseline: 1.6339x; 1.0364x over previous
#include <cuda_runtime.h>
#include <cuda_bf16.h>
#include <math.h>
#include <stdint.h>

#define NN 100000
#define EE 1600000
#define DH 128
#define GG 64
#define CC 10
#define NT 782               // ceil(NN/128)
#define NPAD (NT * 128)      // 100096
#define SCB 98               // scan blocks: ceil(NN/1024)
#define PGRID 148            // persistent MLP grid

// ---------------- scratch (static device arrays; allocation forbidden) ------
__device__ float g_t[NPAD * DH];       // gather output (MLP input); rows>=NN stay 0
__device__ float g_h[NPAD * DH];       // layer output / next gather input
__device__ float g_hpool[NPAD * DH];   // relu(u) after layer 2 for pooling
__device__ __nv_bfloat16 g_Wthi[6 * DH * DH];  // weights transposed [n][k], bf16 hi
__device__ __nv_bfloat16 g_Wtlo[6 * DH * DH];  // bf16 lo plane
__device__ int   g_counts[NN];
__device__ int   g_rowptr[NN + 1];
__device__ int   g_cur[NN];
__device__ int   g_csr_src[EE];
__device__ int   g_bsum[SCB];
__device__ int   g_gstart[GG + 1];
__device__ float g_pool[GG * DH];

// ---------------- helpers ----------------------------------------------------
__device__ __forceinline__ void split2(float a, float b, uint32_t& hw, uint32_t& lw) {
    __nv_bfloat16 ha = __float2bfloat16(a), hb = __float2bfloat16(b);
    float ra = a - __bfloat162float(ha);
    float rb = b - __bfloat162float(hb);
    __nv_bfloat16 la = __float2bfloat16(ra), lb = __float2bfloat16(rb);
    hw = ((uint32_t)__bfloat16_as_ushort(hb) << 16) | __bfloat16_as_ushort(ha);
    lw = ((uint32_t)__bfloat16_as_ushort(lb) << 16) | __bfloat16_as_ushort(la);
}
__device__ __forceinline__ void mma16816(float* c, const uint32_t* a,
                                         uint32_t b0, uint32_t b1) {
    asm("mma.sync.aligned.m16n8k16.row.col.f32.bf16.bf16.f32 "
        "{%0,%1,%2,%3}, {%4,%5,%6,%7}, {%8,%9}, {%0,%1,%2,%3};"
        : "+f"(c[0]), "+f"(c[1]), "+f"(c[2]), "+f"(c[3])
        : "r"(a[0]), "r"(a[1]), "r"(a[2]), "r"(a[3]), "r"(b0), "r"(b1));
}
__device__ __forceinline__ void cp_async16(uint32_t smem_dst, const void* gsrc) {
    asm volatile("cp.async.cg.shared.global [%0], [%1], 16;"
                 :: "r"(smem_dst), "l"(gsrc));
}
__device__ __forceinline__ void cp_async_commit_wait_all() {
    asm volatile("cp.async.commit_group;\n\tcp.async.wait_group 0;" ::: "memory");
}
__device__ __forceinline__ uint32_t smem_u32(const void* p) {
    uint32_t a;
    asm("{ .reg .u64 t; cvta.to.shared.u64 t, %1; cvt.u32.u64 %0, t; }" : "=r"(a) : "l"(p));
    return a;
}

// ---------------- prep: weight convert + zero counts/pool + graph bounds ----
__global__ void prep_kernel(const float* w0, const float* w1, const float* w2,
                            const float* w3, const float* w4, const float* w5,
                            const int* __restrict__ batch) {
    int b = blockIdx.x;
    if (b < 24) {
        const float* ws[6] = {w0, w1, w2, w3, w4, w5};
        int widx = b >> 2, part = b & 3;
        const float* w = ws[widx];
        __nv_bfloat16* hb = g_Wthi + widx * DH * DH;
        __nv_bfloat16* lb = g_Wtlo + widx * DH * DH;
        int end = (part + 1) * 4096;
        for (int idx = part * 4096 + threadIdx.x; idx < end; idx += 256) {
            int n = idx >> 7, k = idx & 127;
            float v = w[k * DH + n];
            __nv_bfloat16 hi = __float2bfloat16(v);
            __nv_bfloat16 lo = __float2bfloat16(v - __bfloat162float(hi));
            hb[idx] = hi;
            lb[idx] = lo;
        }
    } else if (b == 24) {
        for (int i = threadIdx.x; i < GG * DH; i += 256) g_pool[i] = 0.0f;
        int g = threadIdx.x;
        if (g <= GG) {
            int lo = 0, hi = NN;
            while (lo < hi) {
                int mid = (lo + hi) >> 1;
                if (batch[mid] < g) lo = mid + 1; else hi = mid;
            }
            g_gstart[g] = lo;
        }
    } else {
        int i = (b - 25) * 1024 + threadIdx.x;
        #pragma unroll
        for (int q = 0; q < 4; q++) {
            int j = i + q * 256;
            if (j < NN) g_counts[j] = 0;
        }
    }
}

__global__ void count_edges(const int* __restrict__ dst) {
    int e = blockIdx.x * blockDim.x + threadIdx.x;
    if (e < EE) atomicAdd(&g_counts[dst[e]], 1);
}

// ---------------- parallel scan (2 stages, decoupled lookback) --------------
__global__ void scan_stage1() {
    __shared__ int wsum[32];
    int tid = threadIdx.x, lane = tid & 31, w = tid >> 5;
    int i = blockIdx.x * 1024 + tid;
    int v = (i < NN) ? g_counts[i] : 0;
    int s = v;
    #pragma unroll
    for (int o = 1; o < 32; o <<= 1) s += __shfl_xor_sync(0xffffffffu, s, o);
    if (lane == 0) wsum[w] = s;
    __syncthreads();
    if (w == 0) {
        int t = (lane < 32) ? wsum[lane] : 0;
        #pragma unroll
        for (int o = 1; o < 32; o <<= 1) t += __shfl_xor_sync(0xffffffffu, t, o);
        if (lane == 0) g_bsum[blockIdx.x] = t;
    }
}
// each block computes its own lookback over g_bsum (<=98 ints)
__global__ void scan_stage3() {
    __shared__ int wsum[32];
    __shared__ int s_boff;
    int tid = threadIdx.x, lane = tid & 31, w = tid >> 5;
    if (w == 0) {
        int accb = 0;
        for (int j = lane; j < (int)blockIdx.x; j += 32) accb += g_bsum[j];
        #pragma unroll
        for (int o = 1; o < 32; o <<= 1) accb += __shfl_xor_sync(0xffffffffu, accb, o);
        if (lane == 0) s_boff = accb;
    }
    int i = blockIdx.x * 1024 + tid;
    int v = (i < NN) ? g_counts[i] : 0;
    int incl = v;
    #pragma unroll
    for (int o = 1; o < 32; o <<= 1) {
        int t = __shfl_up_sync(0xffffffffu, incl, o);
        if (lane >= o) incl += t;
    }
    if (lane == 31) wsum[w] = incl;
    __syncthreads();
    if (w == 0) {
        int s = wsum[lane];
        #pragma unroll
        for (int o = 1; o < 32; o <<= 1) {
            int t = __shfl_up_sync(0xffffffffu, s, o);
            if (lane >= o) s += t;
        }
        wsum[lane] = s;
    }
    __syncthreads();
    int woff = (w > 0) ? wsum[w - 1] : 0;
    int excl = s_boff + woff + incl - v;
    if (i < NN) {
        g_rowptr[i] = excl;
        g_cur[i] = excl;
    }
    if (blockIdx.x == SCB - 1 && tid == 1023) g_rowptr[NN] = excl;  // v=0 here
}

__global__ void fill_csr(const int* __restrict__ src, const int* __restrict__ dst) {
    int e = blockIdx.x * blockDim.x + threadIdx.x;
    if (e < EE) {
        int p = atomicAdd(&g_cur[dst[e]], 1);
        g_csr_src[p] = src[e];
    }
}

// ---------------- gather (separate launch, high occupancy) ------------------
// t[n] = h[n] + sum_{src in CSR(n)} h[src]
template <bool FIRST>
__global__ void gather_kernel(const float* __restrict__ x) {
    const float* __restrict__ h = FIRST ? x : (const float*)g_h;
    int warp = threadIdx.x >> 5, lane = threadIdx.x & 31;
    int n = blockIdx.x * 8 + warp;
    if (n >= NN) return;
    int off = lane * 4;
    float4 acc = *(const float4*)&h[(size_t)n * DH + off];
    int p = g_rowptr[n], e = g_rowptr[n + 1];
    for (; p + 4 <= e; p += 4) {
        int s0 = g_csr_src[p], s1 = g_csr_src[p + 1];
        int s2 = g_csr_src[p + 2], s3 = g_csr_src[p + 3];
        float4 v0 = *(const float4*)&h[(size_t)s0 * DH + off];
        float4 v1 = *(const float4*)&h[(size_t)s1 * DH + off];
        float4 v2 = *(const float4*)&h[(size_t)s2 * DH + off];
        float4 v3 = *(const float4*)&h[(size_t)s3 * DH + off];
        acc.x += v0.x + v1.x + v2.x + v3.x;
        acc.y += v0.y + v1.y + v2.y + v3.y;
        acc.z += v0.z + v1.z + v2.z + v3.z;
        acc.w += v0.w + v1.w + v2.w + v3.w;
    }
    for (; p < e; ++p) {
        int s = g_csr_src[p];
        float4 v = *(const float4*)&h[(size_t)s * DH + off];
        acc.x += v.x; acc.y += v.y; acc.z += v.z; acc.w += v.w;
    }
    *(float4*)&g_t[(size_t)n * DH + off] = acc;
}

// ---------------- persistent fused MLP kernel --------------------------------
// W planes loaded ONCE per CTA; loop over tiles with stride gridDim.x.
// Per tile: A(g_t) -> split -> GEMM1(+b1,relu) -> split -> GEMM2(+b2) -> epi.
// VAR 0: LN epilogue -> g_h.   VAR 1: emb -> out, relu -> g_hpool.
#define SA_HI 0
#define SA_LO 34816
#define S1_HI 69632
#define S1_LO 104448
#define S2_HI 139264
#define S2_LO 174080
#define SEPI  208896
#define SMEM_DYN (208896 + 768 * 4)
#define PITCHW 68   // smem row pitch in 32-bit words (136 bf16)

template <int VAR>
__global__ void __launch_bounds__(256, 1)
mlp_kernel(int lidx,
           const float* __restrict__ b1v, const float* __restrict__ b2v,
           const float* __restrict__ lng, const float* __restrict__ lnb,
           float* __restrict__ out) {
    extern __shared__ char smem[];
    uint32_t* sah = (uint32_t*)(smem + SA_HI);
    uint32_t* sal = (uint32_t*)(smem + SA_LO);
    float* rowsum = (float*)(smem + SEPI);   // [0:128)
    float* rowsq  = rowsum + 128;            // [128:256)
    float* sb1    = rowsum + 256;            // [256:384)
    float* sb2    = rowsum + 384;            // [384:512)
    float* slg    = rowsum + 512;            // [512:640)
    float* slb    = rowsum + 640;            // [640:768)

    int tid = threadIdx.x;

    // ---- one-time: prefetch W1/W2 planes + params ----
    {
        int wA = 2 * lidx, wB = 2 * lidx + 1;
        const char* w1h = (const char*)((const uint32_t*)g_Wthi + wA * 8192);
        const char* w1l = (const char*)((const uint32_t*)g_Wtlo + wA * 8192);
        const char* w2h = (const char*)((const uint32_t*)g_Wthi + wB * 8192);
        const char* w2l = (const char*)((const uint32_t*)g_Wtlo + wB * 8192);
        uint32_t d1h = smem_u32(smem + S1_HI), d1l = smem_u32(smem + S1_LO);
        uint32_t d2h = smem_u32(smem + S2_HI), d2l = smem_u32(smem + S2_LO);
        for (int i = tid; i < 2048; i += 256) {      // 128 rows x 16 chunks of 16B
            int row = i >> 4, c16 = i & 15;
            uint32_t doff = (row * PITCHW + c16 * 4) * 4;
            cp_async16(d1h + doff, w1h + i * 16);
            cp_async16(d1l + doff, w1l + i * 16);
            cp_async16(d2h + doff, w2h + i * 16);
            cp_async16(d2l + doff, w2l + i * 16);
        }
        if (tid < 128) {
            sb1[tid] = b1v[tid];
            sb2[tid] = b2v[tid];
            if (VAR == 0) {
                slg[tid] = lng[tid];
                slb[tid] = lnb[tid];
            }
        }
        cp_async_commit_wait_all();
    }
    __syncthreads();

    int wid = tid >> 5, lane = tid & 31, g = lane >> 2, t = lane & 3;
    int m0 = (wid >> 1) * 32;       // warp row base (2 m16 tiles)
    int nb = (wid & 1) * 64;        // warp col base (8 n8 tiles)

    for (int tile = blockIdx.x; tile < NT; tile += (int)gridDim.x) {
        // ---- reset LN accumulators + load/split A tile ----
        if (VAR == 0 && tid < 128) { rowsum[tid] = 0.0f; rowsq[tid] = 0.0f; }
        {
            const float* Asrc = (const float*)g_t + (size_t)tile * 128 * DH;
            #pragma unroll
            for (int q = 0; q < 16; q++) {           // 4096 float4s / 256 threads
                int i = q * 256 + tid;
                int row = i >> 5, c4 = (i & 31) * 4;
                float4 v = *(const float4*)(Asrc + row * DH + c4);
                uint32_t hw0, lw0, hw1, lw1;
                split2(v.x, v.y, hw0, lw0);
                split2(v.z, v.w, hw1, lw1);
                int w = row * PITCHW + (c4 >> 1);
                sah[w] = hw0; sah[w + 1] = hw1;
                sal[w] = lw0; sal[w + 1] = lw1;
            }
        }
        __syncthreads();

        float acc[2][8][4];

        // ================= GEMM1 =================
        #pragma unroll
        for (int mi = 0; mi < 2; mi++)
            #pragma unroll
            for (int j = 0; j < 8; j++)
                #pragma unroll
                for (int q = 0; q < 4; q++) acc[mi][j][q] = 0.0f;

        #pragma unroll 1
        for (int pass = 0; pass < 3; pass++) {
            const uint32_t* Ap = (pass == 1) ? sal : sah;
            const uint32_t* Wp = (pass == 2) ? (uint32_t*)(smem + S1_LO)
                                             : (uint32_t*)(smem + S1_HI);
            #pragma unroll
            for (int kk = 0; kk < 8; kk++) {
                int ko = kk * 8 + t;
                uint32_t a[2][4];
                #pragma unroll
                for (int mi = 0; mi < 2; mi++) {
                    int r = m0 + mi * 16 + g;
                    a[mi][0] = Ap[r * PITCHW + ko];
                    a[mi][1] = Ap[(r + 8) * PITCHW + ko];
                    a[mi][2] = Ap[r * PITCHW + ko + 4];
                    a[mi][3] = Ap[(r + 8) * PITCHW + ko + 4];
                }
                #pragma unroll
                for (int j = 0; j < 8; j++) {
                    int n = nb + j * 8 + g;
                    uint32_t b0 = Wp[n * PITCHW + ko];
                    uint32_t b1 = Wp[n * PITCHW + ko + 4];
                    mma16816(acc[0][j], a[0], b0, b1);
                    mma16816(acc[1][j], a[1], b0, b1);
                }
            }
        }
        __syncthreads();   // all warps done reading A planes

        // relu(acc + b1), split back into A planes (C1 tile becomes A2 tile)
        #pragma unroll
        for (int mi = 0; mi < 2; mi++) {
            #pragma unroll
            for (int j = 0; j < 8; j++) {
                int c = nb + j * 8 + t * 2;
                float v0 = fmaxf(acc[mi][j][0] + sb1[c], 0.f);
                float v1 = fmaxf(acc[mi][j][1] + sb1[c + 1], 0.f);
                float v2 = fmaxf(acc[mi][j][2] + sb1[c], 0.f);
                float v3 = fmaxf(acc[mi][j][3] + sb1[c + 1], 0.f);
                uint32_t hw, lw;
                int r0 = m0 + mi * 16 + g;
                int wc = (nb >> 1) + j * 4 + t;
                split2(v0, v1, hw, lw);
                sah[r0 * PITCHW + wc] = hw;
                sal[r0 * PITCHW + wc] = lw;
                split2(v2, v3, hw, lw);
                sah[(r0 + 8) * PITCHW + wc] = hw;
                sal[(r0 + 8) * PITCHW + wc] = lw;
            }
        }
        __syncthreads();

        // ================= GEMM2 =================
        #pragma unroll
        for (int mi = 0; mi < 2; mi++)
            #pragma unroll
            for (int j = 0; j < 8; j++)
                #pragma unroll
                for (int q = 0; q < 4; q++) acc[mi][j][q] = 0.0f;

        #pragma unroll 1
        for (int pass = 0; pass < 3; pass++) {
            const uint32_t* Ap = (pass == 1) ? sal : sah;
            const uint32_t* Wp = (pass == 2) ? (uint32_t*)(smem + S2_LO)
                                             : (uint32_t*)(smem + S2_HI);
            #pragma unroll
            for (int kk = 0; kk < 8; kk++) {
                int ko = kk * 8 + t;
                uint32_t a[2][4];
                #pragma unroll
                for (int mi = 0; mi < 2; mi++) {
                    int r = m0 + mi * 16 + g;
                    a[mi][0] = Ap[r * PITCHW + ko];
                    a[mi][1] = Ap[(r + 8) * PITCHW + ko];
                    a[mi][2] = Ap[r * PITCHW + ko + 4];
                    a[mi][3] = Ap[(r + 8) * PITCHW + ko + 4];
                }
                #pragma unroll
                for (int j = 0; j < 8; j++) {
                    int n = nb + j * 8 + g;
                    uint32_t b0 = Wp[n * PITCHW + ko];
                    uint32_t b1 = Wp[n * PITCHW + ko + 4];
                    mma16816(acc[0][j], a[0], b0, b1);
                    mma16816(acc[1][j], a[1], b0, b1);
                }
            }
        }

        // ---- epilogue ----
        if (VAR == 0) {
            float s[2][2], q[2][2];
            #pragma unroll
            for (int mi = 0; mi < 2; mi++) { s[mi][0]=s[mi][1]=q[mi][0]=q[mi][1]=0.f; }
            #pragma unroll
            for (int mi = 0; mi < 2; mi++)
                #pragma unroll
                for (int j = 0; j < 8; j++) {
                    int c = nb + j * 8 + t * 2;
                    float v0 = fmaxf(acc[mi][j][0] + sb2[c], 0.f);
                    float v1 = fmaxf(acc[mi][j][1] + sb2[c + 1], 0.f);
                    float v2 = fmaxf(acc[mi][j][2] + sb2[c], 0.f);
                    float v3 = fmaxf(acc[mi][j][3] + sb2[c + 1], 0.f);
                    acc[mi][j][0] = v0; acc[mi][j][1] = v1;
                    acc[mi][j][2] = v2; acc[mi][j][3] = v3;
                    s[mi][0] += v0 + v1;  q[mi][0] += v0 * v0 + v1 * v1;
                    s[mi][1] += v2 + v3;  q[mi][1] += v2 * v2 + v3 * v3;
                }
            #pragma unroll
            for (int mi = 0; mi < 2; mi++)
                #pragma unroll
                for (int rh = 0; rh < 2; rh++) {
                    float ss = s[mi][rh], qq = q[mi][rh];
                    ss += __shfl_xor_sync(0xffffffffu, ss, 1);
                    qq += __shfl_xor_sync(0xffffffffu, qq, 1);
                    ss += __shfl_xor_sync(0xffffffffu, ss, 2);
                    qq += __shfl_xor_sync(0xffffffffu, qq, 2);
                    if (t == 0) {
                        int rl = m0 + mi * 16 + rh * 8 + g;
                        atomicAdd(&rowsum[rl], ss);
                        atomicAdd(&rowsq[rl], qq);
                    }
                }
            __syncthreads();
            if (tid < 128) {
                float mean = rowsum[tid] * (1.0f / DH);
                float var = rowsq[tid] * (1.0f / DH) - mean * mean;
                rowsum[tid] = mean;
                rowsq[tid] = rsqrtf(var + 1e-5f);
            }
            __syncthreads();
            #pragma unroll
            for (int mi = 0; mi < 2; mi++)
                #pragma unroll
                for (int rh = 0; rh < 2; rh++) {
                    int rl = m0 + mi * 16 + rh * 8 + g;
                    float mean = rowsum[rl], rs = rowsq[rl];
                    size_t row = (size_t)tile * 128 + rl;
                    #pragma unroll
                    for (int j = 0; j < 8; j++) {
                        int c = nb + j * 8 + t * 2;
                        float v0 = acc[mi][j][rh * 2];
                        float v1 = acc[mi][j][rh * 2 + 1];
                        float2 o;
                        o.x = (v0 - mean) * rs * slg[c] + slb[c];
                        o.y = (v1 - mean) * rs * slg[c + 1] + slb[c + 1];
                        *(float2*)&g_h[row * DH + c] = o;
                    }
                }
        } else {
            #pragma unroll
            for (int mi = 0; mi < 2; mi++)
                #pragma unroll
                for (int rh = 0; rh < 2; rh++) {
                    size_t row = (size_t)tile * 128 + m0 + mi * 16 + rh * 8 + g;
                    if (row < NN) {
                        #pragma unroll
                        for (int j = 0; j < 8; j++) {
                            int c = nb + j * 8 + t * 2;
                            float2 u;
                            u.x = acc[mi][j][rh * 2] + sb2[c];
                            u.y = acc[mi][j][rh * 2 + 1] + sb2[c + 1];
                            *(float2*)&out[row * DH + c] = u;
                            u.x = fmaxf(u.x, 0.f);
                            u.y = fmaxf(u.y, 0.f);
                            *(float2*)&g_hpool[row * DH + c] = u;
                        }
                    }
                }
        }
        __syncthreads();   // planes/rowsum free for next tile
    }
}

// ---------------- pooling + head --------------------------------------------
__global__ void pool_partial() {
    int g = blockIdx.x;
    int chunk = blockIdx.y;
    int f = threadIdx.x;
    int s = g_gstart[g], e = g_gstart[g + 1];
    int len = e - s;
    int per = (len + (int)gridDim.y - 1) / (int)gridDim.y;
    int a = s + chunk * per;
    int b = min(a + per, e);
    float sum = 0.f;
    for (int n = a; n < b; n++) sum += g_hpool[(size_t)n * DH + f];
    if (a < b) atomicAdd(&g_pool[g * DH + f], sum);
}

__global__ void head_mlp(const float* __restrict__ pw1, const float* __restrict__ pb1,
                         const float* __restrict__ pw2, const float* __restrict__ pb2,
                         float* __restrict__ out) {
    __shared__ float sp[DH];
    __shared__ float sz[DH];
    __shared__ float sl[CC];
    int g = blockIdx.x;
    int f = threadIdx.x;
    float cnt = fmaxf((float)(g_gstart[g + 1] - g_gstart[g]), 1.0f);
    sp[f] = g_pool[g * DH + f] / cnt;
    __syncthreads();
    float z = pb1[f];
    #pragma unroll 8
    for (int k = 0; k < DH; k++) z += sp[k] * pw1[k * DH + f];
    sz[f] = z;
    __syncthreads();
    if (f < CC) {
        float l = pb2[f];
        #pragma unroll 8
        for (int k = 0; k < DH; k++) l += sz[k] * pw2[k * CC + f];
        sl[f] = l;
    }
    __syncthreads();
    if (f < CC) {
        float m = -1e30f;
        #pragma unroll
        for (int c = 0; c < CC; c++) m = fmaxf(m, sl[c]);
        float s = 0.f;
        #pragma unroll
        for (int c = 0; c < CC; c++) s += expf(sl[c] - m);
        out[(size_t)NN * DH + g * CC + f] = sl[f] - m - logf(s);
    }
}

// ---------------- launch ----------------------------------------------------
extern "C" void kernel_launch(void* const* d_in, const int* in_sizes, int n_in,
                              void* d_out, int out_size) {
    const float* x    = (const float*)d_in[0];
    const int* eidx   = (const int*)d_in[1];
    const int* batch  = (const int*)d_in[2];
    const float* w1[3] = {(const float*)d_in[3], (const float*)d_in[7], (const float*)d_in[11]};
    const float* b1[3] = {(const float*)d_in[4], (const float*)d_in[8], (const float*)d_in[12]};
    const float* w2[3] = {(const float*)d_in[5], (const float*)d_in[9], (const float*)d_in[13]};
    const float* b2[3] = {(const float*)d_in[6], (const float*)d_in[10], (const float*)d_in[14]};
    const float* ln_g[2] = {(const float*)d_in[15], (const float*)d_in[17]};
    const float* ln_b[2] = {(const float*)d_in[16], (const float*)d_in[18]};
    const float* pw1 = (const float*)d_in[19];
    const float* pb1 = (const float*)d_in[20];
    const float* pw2 = (const float*)d_in[21];
    const float* pb2 = (const float*)d_in[22];
    float* out = (float*)d_out;

    cudaFuncSetAttribute((const void*)mlp_kernel<0>,
                         cudaFuncAttributeMaxDynamicSharedMemorySize, SMEM_DYN);
    cudaFuncSetAttribute((const void*)mlp_kernel<1>,
                         cudaFuncAttributeMaxDynamicSharedMemorySize, SMEM_DYN);

    const int* src = eidx;
    const int* dst = eidx + EE;

    prep_kernel<<<25 + SCB, 256>>>(w1[0], w2[0], w1[1], w2[1], w1[2], w2[2], batch);
    count_edges<<<(EE + 255) / 256, 256>>>(dst);
    scan_stage1<<<SCB, 1024>>>();
    scan_stage3<<<SCB, 1024>>>();
    fill_csr<<<(EE + 255) / 256, 256>>>(src, dst);

    const int node_blocks = (NN + 7) / 8;

    for (int L = 0; L < 3; L++) {
        if (L == 0) gather_kernel<true><<<node_blocks, 256>>>(x);
        else        gather_kernel<false><<<node_blocks, 256>>>(nullptr);
        if (L < 2)
            mlp_kernel<0><<<PGRID, 256, SMEM_DYN>>>(L, b1[L], b2[L], ln_g[L], ln_b[L], nullptr);
        else
            mlp_kernel<1><<<PGRID, 256, SMEM_DYN>>>(L, b1[L], b2[L], nullptr, nullptr, out);
    }

    pool_partial<<<dim3(GG, 16), DH>>>();
    head_mlp<<<GG, DH>>>(pw1, pb1, pw2, pb2, out);
}